// round 7
// baseline (speedup 1.0000x reference)
#include <cuda_runtime.h>

// DisentangledSelfAttention, fully fused fp32, f32x2 packed FMA.
// 2 batch elements per CTA (grid 2048), 256 threads, 8x4 thread tiles over
// stacked [128,64] GEMMs. All operands in smem (LD=64), KhT stored transposed
// (stride 132) so every GEMM is nn with conflict-free loads.

#define ULL unsigned long long

__device__ __forceinline__ ULL pk2(float x, float y) {
    ULL r;
    asm("mov.b64 %0, {%1, %2};" : "=l"(r) : "f"(x), "f"(y));
    return r;
}
__device__ __forceinline__ void fma2(ULL& d, ULL a, ULL b) {
    asm("fma.rn.f32x2 %0, %1, %2, %0;" : "+l"(d) : "l"(a), "l"(b));
}
__device__ __forceinline__ float2 upk(ULL v) {
    float2 r;
    asm("mov.b64 {%0, %1}, %2;" : "=f"(r.x), "=f"(r.y) : "l"(v));
    return r;
}

// acc[p][j]: packed pair = rows (R+2p, R+2p+1), col C+j.
// A row-major stride 64; B row-major stride ldb.
__device__ __forceinline__ void gemm8x4(const float* __restrict__ A,
                                        const float* __restrict__ B, int ldb,
                                        ULL acc[4][4], int R, int C) {
#pragma unroll
    for (int k = 0; k < 64; k += 4) {
        float4 a[8];
#pragma unroll
        for (int i = 0; i < 8; i++) a[i] = *(const float4*)&A[(R + i) * 64 + k];
#pragma unroll
        for (int kk = 0; kk < 4; kk++) {
            float4 b4 = *(const float4*)&B[(k + kk) * ldb + C];
            ULL bd0 = pk2(b4.x, b4.x), bd1 = pk2(b4.y, b4.y);
            ULL bd2 = pk2(b4.z, b4.z), bd3 = pk2(b4.w, b4.w);
#pragma unroll
            for (int p = 0; p < 4; p++) {
                const float* alo = (const float*)&a[2 * p];
                const float* ahi = (const float*)&a[2 * p + 1];
                ULL ap = pk2(alo[kk], ahi[kk]);
                fma2(acc[p][0], ap, bd0);
                fma2(acc[p][1], ap, bd1);
                fma2(acc[p][2], ap, bd2);
                fma2(acc[p][3], ap, bd3);
            }
        }
    }
}

__device__ __forceinline__ void init_tile(ULL acc[4][4], float v0, float v1,
                                          float v2, float v3) {
    ULL a0 = pk2(v0, v0), a1 = pk2(v1, v1), a2 = pk2(v2, v2), a3 = pk2(v3, v3);
#pragma unroll
    for (int p = 0; p < 4; p++) {
        acc[p][0] = a0; acc[p][1] = a1; acc[p][2] = a2; acc[p][3] = a3;
    }
}

__device__ __forceinline__ void store_tile(float* __restrict__ dst,
                                           ULL acc[4][4], int R, int C) {
#pragma unroll
    for (int p = 0; p < 4; p++) {
        float2 c0 = upk(acc[p][0]), c1 = upk(acc[p][1]);
        float2 c2 = upk(acc[p][2]), c3 = upk(acc[p][3]);
        *(float4*)&dst[(R + 2 * p) * 64 + C]     = make_float4(c0.x, c1.x, c2.x, c3.x);
        *(float4*)&dst[(R + 2 * p + 1) * 64 + C] = make_float4(c0.y, c1.y, c2.y, c3.y);
    }
}

// dst[e*64 + c] = W[e*256 + hc + c],  e,c in [0,64)
__device__ __forceinline__ void stage_w(float* __restrict__ dst,
                                        const float* __restrict__ W,
                                        int hc, int tid) {
#pragma unroll
    for (int it = 0; it < 4; it++) {
        int i = tid + (it << 8);
        int e = i >> 4, c = (i & 15) << 2;
        *(float4*)&dst[(e << 6) + c] = *(const float4*)&W[(e << 8) + hc + c];
    }
}

// smem offsets (floats)
#define O_QIN  0
#define O_KIN  8192
#define O_VIN  16384
#define O_W    24576
#define O_QH   28672
#define O_KHT  36864        // [64][132]
#define O_VH   45312
#define O_MQ   53504        // [2][64]
#define O_QC   53632        // [2][256]
#define O_USM  54144        // [2][4][64]
#define O_WU   54656        // [64][4]
#define SM_FLOATS 54912

__global__ __launch_bounds__(256, 1)
void disattn_kernel(const float* __restrict__ query,
                    const float* __restrict__ key_,
                    const float* __restrict__ value,
                    const float* __restrict__ Wq, const float* __restrict__ bq,
                    const float* __restrict__ Wk, const float* __restrict__ bk,
                    const float* __restrict__ Wv, const float* __restrict__ bv,
                    const float* __restrict__ Wu, const float* __restrict__ bu,
                    const float* __restrict__ Wr, const float* __restrict__ br,
                    float* __restrict__ out) {
    extern __shared__ float sm[];
    float* sQin = sm + O_QIN;
    float* sKin = sm + O_KIN;
    float* sVin = sm + O_VIN;
    float* sW   = sm + O_W;
    float* sQh  = sm + O_QH;    // Q-head, then scores/attn
    float* sKhT = sm + O_KHT;   // K-head transposed [d][s], stride 132
    float* sVh  = sm + O_VH;
    float* mq   = sm + O_MQ;
    float* qc   = sm + O_QC;
    float* susm = sm + O_USM;
    float* sWu  = sm + O_WU;

    const int tid = threadIdx.x;
    const int b0 = blockIdx.x << 1;
    const int tx = tid & 15, ty = tid >> 4;
    const int R = ty << 3, C = tx << 2;
    const int batch = R >> 6;            // 0 or 1

    const float* qg = query + (size_t)b0 * 4096;
    const float* kg = key_  + (size_t)b0 * 4096;
    const float* vg = value + (size_t)b0 * 4096;

    // Stage inputs (2 batches contiguous = 8192 floats each) + Wu.
#pragma unroll
    for (int it = 0; it < 8; it++) {
        int i4 = (tid + (it << 8)) << 2;
        *(float4*)&sQin[i4] = *(const float4*)&qg[i4];
        *(float4*)&sKin[i4] = *(const float4*)&kg[i4];
        *(float4*)&sVin[i4] = *(const float4*)&vg[i4];
    }
    if (tid < 64)
        *(float4*)&sWu[tid << 2] = *(const float4*)&Wu[tid << 2];
    __syncthreads();

    // Unary logits u[b][h][s] (rotated float4 reads) + query row-means mq[b][e].
#pragma unroll
    for (int u = 0; u < 2; u++) {
        int slot = tid + (u << 8);
        int s = slot & 63, h = (slot >> 6) & 3, bb = slot >> 8;
        const float* kr = &sKin[((bb << 6) + s) << 6];
        float acc = __ldg(&bu[h]);
#pragma unroll
        for (int cc = 0; cc < 16; cc++) {
            int c4 = ((cc + s) & 15) << 2;
            float4 kv = *(const float4*)&kr[c4];
            acc = fmaf(kv.x, sWu[((c4 + 0) << 2) + h], acc);
            acc = fmaf(kv.y, sWu[((c4 + 1) << 2) + h], acc);
            acc = fmaf(kv.z, sWu[((c4 + 2) << 2) + h], acc);
            acc = fmaf(kv.w, sWu[((c4 + 3) << 2) + h], acc);
        }
        susm[((bb << 2) + h) * 64 + s] = acc;
    }
    if (tid < 128) {
        int bb = tid >> 6, e = tid & 63;
        float s = 0.0f;
#pragma unroll
        for (int r = 0; r < 64; r++) s += sQin[((bb << 6) + r) * 64 + e];
        mq[tid] = s * (1.0f / 64.0f);
    }
    __syncthreads();

    // Unary softmax over s, one warp per (b,h).
    {
        int w = tid >> 5, lane = tid & 31;
        float v0 = susm[(w << 6) + lane];
        float v1 = susm[(w << 6) + 32 + lane];
        float m = fmaxf(v0, v1);
#pragma unroll
        for (int d = 16; d; d >>= 1)
            m = fmaxf(m, __shfl_xor_sync(0xffffffffu, m, d));
        float e0 = __expf(v0 - m), e1 = __expf(v1 - m);
        float s2 = e0 + e1;
#pragma unroll
        for (int d = 16; d; d >>= 1)
            s2 += __shfl_xor_sync(0xffffffffu, s2, d);
        float inv = 1.0f / s2;
        susm[(w << 6) + lane]      = e0 * inv;
        susm[(w << 6) + 32 + lane] = e1 * inv;
    }
    __syncthreads();

    // qc[b][a] = mq[b] @ Wq[:,a]  (Q-centering; bq cancels exactly)
#pragma unroll
    for (int u = 0; u < 2; u++) {
        int slot = tid + (u << 8);
        int bb = slot >> 8, aa = slot & 255;
        const float* mqb = &mq[bb << 6];
        float acc = 0.0f;
#pragma unroll
        for (int e = 0; e < 64; e++)
            acc = fmaf(mqb[e], __ldg(&Wq[(e << 8) + aa]), acc);
        qc[slot] = acc;
    }
    __syncthreads();

#pragma unroll 1
    for (int h = 0; h < 4; h++) {
        const int hc = h << 6;

        // Q-head (centered): qin @ WqSlice - qc
        stage_w(sW, Wq, hc, tid);
        __syncthreads();
        {
            ULL acc[4][4];
            const float* qcb = &qc[(batch << 8) + hc + C];
            init_tile(acc, -qcb[0], -qcb[1], -qcb[2], -qcb[3]);
            gemm8x4(sQin, sW, 64, acc, R, C);
            store_tile(sQh, acc, R, C);
        }
        __syncthreads();

        // K-head (no bias, no centering needed) -> transposed store
        stage_w(sW, Wk, hc, tid);
        __syncthreads();
        {
            ULL acc[4][4];
            init_tile(acc, 0.0f, 0.0f, 0.0f, 0.0f);
            gemm8x4(sKin, sW, 64, acc, R, C);
#pragma unroll
            for (int p = 0; p < 4; p++)
#pragma unroll
                for (int j = 0; j < 4; j++) {
                    float2 v = upk(acc[p][j]);
                    *(float2*)&sKhT[(C + j) * 132 + R + 2 * p] = v;
                }
        }
        __syncthreads();

        // V-head (+ bv)
        stage_w(sW, Wv, hc, tid);
        __syncthreads();
        {
            ULL acc[4][4];
            init_tile(acc, __ldg(&bv[hc + C + 0]), __ldg(&bv[hc + C + 1]),
                      __ldg(&bv[hc + C + 2]), __ldg(&bv[hc + C + 3]));
            gemm8x4(sVin, sW, 64, acc, R, C);
            store_tile(sVh, acc, R, C);
        }
        __syncthreads();

        // scores = Qt @ K^T  (per batch), into registers
        ULL sacc[4][4];
        init_tile(sacc, 0.0f, 0.0f, 0.0f, 0.0f);
        gemm8x4(sQh, sKhT + (batch << 6), 132, sacc, R, C);
        __syncthreads();                    // all Qh/KhT reads complete
        store_tile(sQh, sacc, R, C);        // scores overwrite Qh
        stage_w(sW, Wr, hc, tid);           // Wr slice (sW is dead)
        __syncthreads();

        // Row softmax + unary add (2 threads/row, rotated float4 access)
        {
            int row = tid >> 1, half = tid & 1;
            int bb2 = row >> 6;
            float* sr = &sQh[(row << 6) + (half << 5)];
            const float* ur = &susm[((bb2 << 2) + h) << 6] + (half << 5);
            int rot = row & 7;
            float4 v[8];
#pragma unroll
            for (int cc = 0; cc < 8; cc++) {
                int c4 = ((cc + rot) & 7) << 2;
                v[cc] = *(const float4*)&sr[c4];
            }
            float m = -1e30f;
#pragma unroll
            for (int cc = 0; cc < 8; cc++) {
                m = fmaxf(m, fmaxf(fmaxf(v[cc].x, v[cc].y), fmaxf(v[cc].z, v[cc].w)));
            }
            m = fmaxf(m, __shfl_xor_sync(0xffffffffu, m, 1));
            float ssum = 0.0f;
#pragma unroll
            for (int cc = 0; cc < 8; cc++) {
                v[cc].x = __expf(v[cc].x - m);
                v[cc].y = __expf(v[cc].y - m);
                v[cc].z = __expf(v[cc].z - m);
                v[cc].w = __expf(v[cc].w - m);
                ssum += v[cc].x + v[cc].y + v[cc].z + v[cc].w;
            }
            ssum += __shfl_xor_sync(0xffffffffu, ssum, 1);
            float inv = 1.0f / ssum;
#pragma unroll
            for (int cc = 0; cc < 8; cc++) {
                int c4 = ((cc + rot) & 7) << 2;
                float4 u4 = *(const float4*)&ur[c4];
                float4 o;
                o.x = fmaf(v[cc].x, inv, u4.x);
                o.y = fmaf(v[cc].y, inv, u4.y);
                o.z = fmaf(v[cc].z, inv, u4.z);
                o.w = fmaf(v[cc].w, inv, u4.w);
                *(float4*)&sr[c4] = o;
            }
        }
        __syncthreads();

        // out = attn @ Vh + qin @ WrSlice + br
        {
            ULL acc[4][4];
            init_tile(acc, __ldg(&br[hc + C + 0]), __ldg(&br[hc + C + 1]),
                      __ldg(&br[hc + C + 2]), __ldg(&br[hc + C + 3]));
            gemm8x4(sQh, sVh + (batch << 12), 64, acc, R, C);
            gemm8x4(sQin, sW, 64, acc, R, C);

            float* og = out + (size_t)(b0 + batch) * 16384 + (R & 63) * 256 + hc + C;
#pragma unroll
            for (int p = 0; p < 4; p++) {
                float2 c0 = upk(acc[p][0]), c1 = upk(acc[p][1]);
                float2 c2 = upk(acc[p][2]), c3 = upk(acc[p][3]);
                *(float4*)&og[(2 * p) * 256]     = make_float4(c0.x, c1.x, c2.x, c3.x);
                *(float4*)&og[(2 * p + 1) * 256] = make_float4(c0.y, c1.y, c2.y, c3.y);
            }
        }
        __syncthreads();
    }
}

extern "C" void kernel_launch(void* const* d_in, const int* in_sizes, int n_in,
                              void* d_out, int out_size) {
    const float* query = (const float*)d_in[0];
    const float* key_  = (const float*)d_in[1];
    const float* value = (const float*)d_in[2];
    const float* Wq    = (const float*)d_in[3];
    const float* bq    = (const float*)d_in[4];
    const float* Wk    = (const float*)d_in[5];
    const float* bk    = (const float*)d_in[6];
    const float* Wv    = (const float*)d_in[7];
    const float* bv    = (const float*)d_in[8];
    const float* Wu    = (const float*)d_in[9];
    const float* bu    = (const float*)d_in[10];
    const float* Wr    = (const float*)d_in[11];
    const float* br    = (const float*)d_in[12];
    float* out = (float*)d_out;
    (void)bq; (void)bk;

    size_t smem = SM_FLOATS * sizeof(float);   // ~214.5 KB
    cudaFuncSetAttribute(disattn_kernel,
                         cudaFuncAttributeMaxDynamicSharedMemorySize, (int)smem);
    disattn_kernel<<<2048, 256, smem>>>(query, key_, value, Wq, bq, Wk, bk,
                                        Wv, bv, Wu, bu, Wr, br, out);
}

// round 11
// speedup vs baseline: 1.1096x; 1.1096x over previous
#include <cuda_runtime.h>

// DisentangledSelfAttention, fully fused fp32, plain-FFMA 8x4 thread tiles.
// 2 batch elements per CTA (grid 2048), 256 threads, stacked [128,64] GEMMs.
// All operands in smem (LD=64), KhT stored transposed (stride 132) so every
// GEMM is nn with conflict-free loads. Algebraic eliminations: K-centering
// and bk dropped (softmax-invariant); Q-centering folded via qc = mean(q)@Wq
// (bq cancels exactly).

// acc[i][j] += sum_k A[(R+i)*64+k] * B[k*ldb + C+j]
__device__ __forceinline__ void gemm8x4(const float* __restrict__ A,
                                        const float* __restrict__ B, int ldb,
                                        float acc[8][4], int R, int C) {
#pragma unroll
    for (int k = 0; k < 64; k += 4) {
        float4 a[8];
#pragma unroll
        for (int i = 0; i < 8; i++) a[i] = *(const float4*)&A[(R + i) * 64 + k];
#pragma unroll
        for (int kk = 0; kk < 4; kk++) {
            float4 b4 = *(const float4*)&B[(k + kk) * ldb + C];
#pragma unroll
            for (int i = 0; i < 8; i++) {
                float av = (kk == 0) ? a[i].x : (kk == 1) ? a[i].y
                         : (kk == 2) ? a[i].z : a[i].w;
                acc[i][0] = fmaf(av, b4.x, acc[i][0]);
                acc[i][1] = fmaf(av, b4.y, acc[i][1]);
                acc[i][2] = fmaf(av, b4.z, acc[i][2]);
                acc[i][3] = fmaf(av, b4.w, acc[i][3]);
            }
        }
    }
}

__device__ __forceinline__ void init_tile(float acc[8][4], float v0, float v1,
                                          float v2, float v3) {
#pragma unroll
    for (int i = 0; i < 8; i++) {
        acc[i][0] = v0; acc[i][1] = v1; acc[i][2] = v2; acc[i][3] = v3;
    }
}

__device__ __forceinline__ void store_tile(float* __restrict__ dst,
                                           float acc[8][4], int R, int C) {
#pragma unroll
    for (int i = 0; i < 8; i++)
        *(float4*)&dst[(R + i) * 64 + C] =
            make_float4(acc[i][0], acc[i][1], acc[i][2], acc[i][3]);
}

// dst[e*64 + c] = W[e*256 + hc + c],  e,c in [0,64)
__device__ __forceinline__ void stage_w(float* __restrict__ dst,
                                        const float* __restrict__ W,
                                        int hc, int tid) {
#pragma unroll
    for (int it = 0; it < 4; it++) {
        int i = tid + (it << 8);
        int e = i >> 4, c = (i & 15) << 2;
        *(float4*)&dst[(e << 6) + c] = *(const float4*)&W[(e << 8) + hc + c];
    }
}

// smem offsets (floats)
#define O_QIN  0
#define O_KIN  8192
#define O_VIN  16384
#define O_W    24576
#define O_QH   28672
#define O_KHT  36864        // [64][132]
#define O_VH   45312
#define O_MQ   53504        // [2][64]
#define O_QC   53632        // [2][256]
#define O_USM  54144        // [2][4][64]
#define O_WU   54656        // [64][4]
#define SM_FLOATS 54912

__global__ __launch_bounds__(256, 1)
void disattn_kernel(const float* __restrict__ query,
                    const float* __restrict__ key_,
                    const float* __restrict__ value,
                    const float* __restrict__ Wq, const float* __restrict__ bq,
                    const float* __restrict__ Wk, const float* __restrict__ bk,
                    const float* __restrict__ Wv, const float* __restrict__ bv,
                    const float* __restrict__ Wu, const float* __restrict__ bu,
                    const float* __restrict__ Wr, const float* __restrict__ br,
                    float* __restrict__ out) {
    extern __shared__ float sm[];
    float* sQin = sm + O_QIN;
    float* sKin = sm + O_KIN;
    float* sVin = sm + O_VIN;
    float* sW   = sm + O_W;
    float* sQh  = sm + O_QH;    // Q-head, then scores/attn
    float* sKhT = sm + O_KHT;   // K-head transposed [d][s], stride 132
    float* sVh  = sm + O_VH;
    float* mq   = sm + O_MQ;
    float* qc   = sm + O_QC;
    float* susm = sm + O_USM;
    float* sWu  = sm + O_WU;

    const int tid = threadIdx.x;
    const int b0 = blockIdx.x << 1;
    const int tx = tid & 15, ty = tid >> 4;
    const int R = ty << 3, C = tx << 2;
    const int batch = R >> 6;            // 0 or 1

    const float* qg = query + (size_t)b0 * 4096;
    const float* kg = key_  + (size_t)b0 * 4096;
    const float* vg = value + (size_t)b0 * 4096;

    // Stage inputs (2 batches contiguous = 8192 floats each) + Wu.
#pragma unroll
    for (int it = 0; it < 8; it++) {
        int i4 = (tid + (it << 8)) << 2;
        *(float4*)&sQin[i4] = *(const float4*)&qg[i4];
        *(float4*)&sKin[i4] = *(const float4*)&kg[i4];
        *(float4*)&sVin[i4] = *(const float4*)&vg[i4];
    }
    if (tid < 64)
        *(float4*)&sWu[tid << 2] = *(const float4*)&Wu[tid << 2];
    __syncthreads();

    // Unary logits u[b][h][s] (rotated float4 reads) + query row-means mq[b][e].
#pragma unroll
    for (int u = 0; u < 2; u++) {
        int slot = tid + (u << 8);
        int s = slot & 63, h = (slot >> 6) & 3, bb = slot >> 8;
        const float* kr = &sKin[((bb << 6) + s) << 6];
        float acc = __ldg(&bu[h]);
#pragma unroll
        for (int cc = 0; cc < 16; cc++) {
            int c4 = ((cc + s) & 15) << 2;
            float4 kv = *(const float4*)&kr[c4];
            acc = fmaf(kv.x, sWu[((c4 + 0) << 2) + h], acc);
            acc = fmaf(kv.y, sWu[((c4 + 1) << 2) + h], acc);
            acc = fmaf(kv.z, sWu[((c4 + 2) << 2) + h], acc);
            acc = fmaf(kv.w, sWu[((c4 + 3) << 2) + h], acc);
        }
        susm[((bb << 2) + h) * 64 + s] = acc;
    }
    if (tid < 128) {
        int bb = tid >> 6, e = tid & 63;
        float s = 0.0f;
#pragma unroll
        for (int r = 0; r < 64; r++) s += sQin[((bb << 6) + r) * 64 + e];
        mq[tid] = s * (1.0f / 64.0f);
    }
    __syncthreads();

    // Unary softmax over s, one warp per (b,h).
    {
        int w = tid >> 5, lane = tid & 31;
        float v0 = susm[(w << 6) + lane];
        float v1 = susm[(w << 6) + 32 + lane];
        float m = fmaxf(v0, v1);
#pragma unroll
        for (int d = 16; d; d >>= 1)
            m = fmaxf(m, __shfl_xor_sync(0xffffffffu, m, d));
        float e0 = __expf(v0 - m), e1 = __expf(v1 - m);
        float s2 = e0 + e1;
#pragma unroll
        for (int d = 16; d; d >>= 1)
            s2 += __shfl_xor_sync(0xffffffffu, s2, d);
        float inv = 1.0f / s2;
        susm[(w << 6) + lane]      = e0 * inv;
        susm[(w << 6) + 32 + lane] = e1 * inv;
    }
    __syncthreads();

    // qc[b][a] = mq[b] @ Wq[:,a]  (Q-centering; bq cancels exactly)
#pragma unroll
    for (int u = 0; u < 2; u++) {
        int slot = tid + (u << 8);
        int bb = slot >> 8, aa = slot & 255;
        const float* mqb = &mq[bb << 6];
        float acc = 0.0f;
#pragma unroll
        for (int e = 0; e < 64; e++)
            acc = fmaf(mqb[e], __ldg(&Wq[(e << 8) + aa]), acc);
        qc[slot] = acc;
    }
    __syncthreads();

#pragma unroll 1
    for (int h = 0; h < 4; h++) {
        const int hc = h << 6;

        // Q-head (centered): qin @ WqSlice - qc
        stage_w(sW, Wq, hc, tid);
        __syncthreads();
        {
            float acc[8][4];
            const float* qcb = &qc[(batch << 8) + hc + C];
            init_tile(acc, -qcb[0], -qcb[1], -qcb[2], -qcb[3]);
            gemm8x4(sQin, sW, 64, acc, R, C);
            store_tile(sQh, acc, R, C);
        }
        __syncthreads();

        // K-head (no bias, no centering needed) -> transposed store
        stage_w(sW, Wk, hc, tid);
        __syncthreads();
        {
            float acc[8][4];
            init_tile(acc, 0.0f, 0.0f, 0.0f, 0.0f);
            gemm8x4(sKin, sW, 64, acc, R, C);
#pragma unroll
            for (int i = 0; i < 8; i++)
#pragma unroll
                for (int j = 0; j < 4; j++)
                    sKhT[(C + j) * 132 + R + i] = acc[i][j];
        }
        __syncthreads();

        // V-head (+ bv)
        stage_w(sW, Wv, hc, tid);
        __syncthreads();
        {
            float acc[8][4];
            init_tile(acc, __ldg(&bv[hc + C + 0]), __ldg(&bv[hc + C + 1]),
                      __ldg(&bv[hc + C + 2]), __ldg(&bv[hc + C + 3]));
            gemm8x4(sVin, sW, 64, acc, R, C);
            store_tile(sVh, acc, R, C);
        }
        __syncthreads();

        // scores = Qt @ K^T  (per batch), into registers
        {
            float sacc[8][4];
            init_tile(sacc, 0.0f, 0.0f, 0.0f, 0.0f);
            gemm8x4(sQh, sKhT + (batch << 6), 132, sacc, R, C);
            __syncthreads();                    // all Qh/KhT reads complete
            store_tile(sQh, sacc, R, C);        // scores overwrite Qh
        }
        stage_w(sW, Wr, hc, tid);               // Wr slice (sW is dead)
        __syncthreads();

        // Row softmax + unary add (2 threads/row, rotated float4 access)
        {
            int row = tid >> 1, half = tid & 1;
            int bb2 = row >> 6;
            float* sr = &sQh[(row << 6) + (half << 5)];
            const float* ur = &susm[((bb2 << 2) + h) << 6] + (half << 5);
            int rot = row & 7;
            float4 v[8];
#pragma unroll
            for (int cc = 0; cc < 8; cc++) {
                int c4 = ((cc + rot) & 7) << 2;
                v[cc] = *(const float4*)&sr[c4];
            }
            float m = -1e30f;
#pragma unroll
            for (int cc = 0; cc < 8; cc++) {
                m = fmaxf(m, fmaxf(fmaxf(v[cc].x, v[cc].y), fmaxf(v[cc].z, v[cc].w)));
            }
            m = fmaxf(m, __shfl_xor_sync(0xffffffffu, m, 1));
            float ssum = 0.0f;
#pragma unroll
            for (int cc = 0; cc < 8; cc++) {
                v[cc].x = __expf(v[cc].x - m);
                v[cc].y = __expf(v[cc].y - m);
                v[cc].z = __expf(v[cc].z - m);
                v[cc].w = __expf(v[cc].w - m);
                ssum += v[cc].x + v[cc].y + v[cc].z + v[cc].w;
            }
            ssum += __shfl_xor_sync(0xffffffffu, ssum, 1);
            float inv = 1.0f / ssum;
#pragma unroll
            for (int cc = 0; cc < 8; cc++) {
                int c4 = ((cc + rot) & 7) << 2;
                float4 u4 = *(const float4*)&ur[c4];
                float4 o;
                o.x = fmaf(v[cc].x, inv, u4.x);
                o.y = fmaf(v[cc].y, inv, u4.y);
                o.z = fmaf(v[cc].z, inv, u4.z);
                o.w = fmaf(v[cc].w, inv, u4.w);
                *(float4*)&sr[c4] = o;
            }
        }
        __syncthreads();

        // out = attn @ Vh + qin @ WrSlice + br
        {
            float acc[8][4];
            init_tile(acc, __ldg(&br[hc + C + 0]), __ldg(&br[hc + C + 1]),
                      __ldg(&br[hc + C + 2]), __ldg(&br[hc + C + 3]));
            gemm8x4(sQh, sVh + (batch << 12), 64, acc, R, C);
            gemm8x4(sQin, sW, 64, acc, R, C);

            float* og = out + (size_t)(b0 + batch) * 16384 + (R & 63) * 256 + hc + C;
#pragma unroll
            for (int i = 0; i < 8; i++)
                *(float4*)&og[i * 256] =
                    make_float4(acc[i][0], acc[i][1], acc[i][2], acc[i][3]);
        }
        __syncthreads();
    }
}

extern "C" void kernel_launch(void* const* d_in, const int* in_sizes, int n_in,
                              void* d_out, int out_size) {
    const float* query = (const float*)d_in[0];
    const float* key_  = (const float*)d_in[1];
    const float* value = (const float*)d_in[2];
    const float* Wq    = (const float*)d_in[3];
    const float* bq    = (const float*)d_in[4];
    const float* Wk    = (const float*)d_in[5];
    const float* bk    = (const float*)d_in[6];
    const float* Wv    = (const float*)d_in[7];
    const float* bv    = (const float*)d_in[8];
    const float* Wu    = (const float*)d_in[9];
    const float* bu    = (const float*)d_in[10];
    const float* Wr    = (const float*)d_in[11];
    const float* br    = (const float*)d_in[12];
    float* out = (float*)d_out;
    (void)bq; (void)bk;

    size_t smem = SM_FLOATS * sizeof(float);   // ~214.5 KB
    cudaFuncSetAttribute(disattn_kernel,
                         cudaFuncAttributeMaxDynamicSharedMemorySize, (int)smem);
    disattn_kernel<<<2048, 256, smem>>>(query, key_, value, Wq, bq, Wk, bk,
                                        Wv, bv, Wu, bu, Wr, br, out);
}

// round 12
// speedup vs baseline: 1.6583x; 1.4945x over previous
#include <cuda_runtime.h>

// DisentangledSelfAttention, fused fp32, occupancy-oriented:
// 1 batch per CTA (grid 4096), 128 threads, ~70KB smem -> 3 CTAs/SM.
// Only the query tile is smem-resident; K/V A-operands are read from global
// (warp-broadcast LDG, L2-hot after head 0). Work buffers rotate roles.
// Algebra: K-centering + bk dropped (softmax-invariant); Q-centering folded
// via qc = mean(q)@Wq (bq cancels exactly).

#define LDW  68   // stage + QH stride (float4-aligned, conflict-free)
#define LDKV 66   // KhT/Vh stride (float2-aligned, 4-way store conflicts only)

#define O_QIN 0
#define O_ST  4096
#define O_QH  (O_ST + 64 * LDW)     // 8448
#define O_KV  (O_QH + 64 * LDW)     // 12800
#define O_MQ  (O_KV + 64 * LDKV)    // 17024
#define O_QC  (O_MQ + 64)           // 17088
#define O_USM (O_QC + 256)          // 17344
#define O_WU  (O_USM + 256)         // 17600
#define SM_FLOATS (O_WU + 256)      // 17856 floats = 71424 B

// A (smem or global, row stride lda) x B (smem, stride ldb, float4 reads).
// Register double-buffered A prefetch to hide LDG latency.
__device__ __forceinline__ void gemm4(const float* __restrict__ A, int lda,
                                      const float* __restrict__ B, int ldb,
                                      float acc[8][4], int R, int C) {
    float4 a0[8], a1[8];
#pragma unroll
    for (int i = 0; i < 8; i++) a0[i] = *(const float4*)&A[(R + i) * lda];
#pragma unroll
    for (int k = 0; k < 64; k += 4) {
        float4* ac = ((k >> 2) & 1) ? a1 : a0;
        float4* an = ((k >> 2) & 1) ? a0 : a1;
        if (k < 60) {
#pragma unroll
            for (int i = 0; i < 8; i++)
                an[i] = *(const float4*)&A[(R + i) * lda + k + 4];
        }
#pragma unroll
        for (int kk = 0; kk < 4; kk++) {
            float4 b4 = *(const float4*)&B[(k + kk) * ldb + C];
#pragma unroll
            for (int i = 0; i < 8; i++) {
                float av = (kk == 0) ? ac[i].x : (kk == 1) ? ac[i].y
                         : (kk == 2) ? ac[i].z : ac[i].w;
                acc[i][0] = fmaf(av, b4.x, acc[i][0]);
                acc[i][1] = fmaf(av, b4.y, acc[i][1]);
                acc[i][2] = fmaf(av, b4.z, acc[i][2]);
                acc[i][3] = fmaf(av, b4.w, acc[i][3]);
            }
        }
    }
}

// A (smem, stride lda, float4) x B (smem, stride ldb, float2 reads; ldb even).
__device__ __forceinline__ void gemm2(const float* __restrict__ A, int lda,
                                      const float* __restrict__ B, int ldb,
                                      float acc[8][4], int R, int C) {
#pragma unroll
    for (int k = 0; k < 64; k += 4) {
        float4 a[8];
#pragma unroll
        for (int i = 0; i < 8; i++) a[i] = *(const float4*)&A[(R + i) * lda + k];
#pragma unroll
        for (int kk = 0; kk < 4; kk++) {
            float2 bl = *(const float2*)&B[(k + kk) * ldb + C];
            float2 bh = *(const float2*)&B[(k + kk) * ldb + C + 2];
#pragma unroll
            for (int i = 0; i < 8; i++) {
                float av = (kk == 0) ? a[i].x : (kk == 1) ? a[i].y
                         : (kk == 2) ? a[i].z : a[i].w;
                acc[i][0] = fmaf(av, bl.x, acc[i][0]);
                acc[i][1] = fmaf(av, bl.y, acc[i][1]);
                acc[i][2] = fmaf(av, bh.x, acc[i][2]);
                acc[i][3] = fmaf(av, bh.y, acc[i][3]);
            }
        }
    }
}

__device__ __forceinline__ void init_tile(float acc[8][4], float v0, float v1,
                                          float v2, float v3) {
#pragma unroll
    for (int i = 0; i < 8; i++) {
        acc[i][0] = v0; acc[i][1] = v1; acc[i][2] = v2; acc[i][3] = v3;
    }
}

// float4 store, stride LDW (conflict-free).
__device__ __forceinline__ void store_w(float* __restrict__ dst,
                                        float acc[8][4], int R, int C) {
#pragma unroll
    for (int i = 0; i < 8; i++)
        *(float4*)&dst[(R + i) * LDW + C] =
            make_float4(acc[i][0], acc[i][1], acc[i][2], acc[i][3]);
}

// dst[e*LDW + c] = W[e*256 + hc + c],  e,c in [0,64); 128 threads.
__device__ __forceinline__ void stage_w(float* __restrict__ dst,
                                        const float* __restrict__ W,
                                        int hc, int tid) {
#pragma unroll
    for (int it = 0; it < 8; it++) {
        int i = tid + (it << 7);
        int e = i >> 4, c = (i & 15) << 2;
        *(float4*)&dst[e * LDW + c] = *(const float4*)&W[(e << 8) + hc + c];
    }
}

__global__ __launch_bounds__(128, 3)
void disattn_kernel(const float* __restrict__ query,
                    const float* __restrict__ key_,
                    const float* __restrict__ value,
                    const float* __restrict__ Wq, const float* __restrict__ bq,
                    const float* __restrict__ Wk, const float* __restrict__ bk,
                    const float* __restrict__ Wv, const float* __restrict__ bv,
                    const float* __restrict__ Wu, const float* __restrict__ bu,
                    const float* __restrict__ Wr, const float* __restrict__ br,
                    float* __restrict__ out) {
    extern __shared__ float sm[];
    float* sQin = sm + O_QIN;   // [64][64] query tile (resident)
    float* sST  = sm + O_ST;    // [64][LDW]: Wq/Wk/Wv/Wr staging, scores/attn
    float* sQH  = sm + O_QH;    // [64][LDW]: Qh, then Wv/Wr staging host
    float* sKV  = sm + O_KV;    // [64][LDKV]: KhT, then Vh
    float* mq   = sm + O_MQ;    // [64]
    float* qc   = sm + O_QC;    // [256]
    float* susm = sm + O_USM;   // [4][64]
    float* sWu  = sm + O_WU;    // [64][4]

    const int tid = threadIdx.x;
    const int b = blockIdx.x;
    const int tx = tid & 15, ty = tid >> 4;
    const int R = ty << 3, C = tx << 2;

    const float* qg = query + (size_t)b * 4096;
    const float* kg = key_  + (size_t)b * 4096;
    const float* vg = value + (size_t)b * 4096;

    // Prologue: stage query tile + Wu.
#pragma unroll
    for (int it = 0; it < 8; it++) {
        int i4 = (tid + (it << 7)) << 2;
        *(float4*)&sQin[i4] = *(const float4*)&qg[i4];
    }
    if (tid < 64)
        *(float4*)&sWu[tid << 2] = *(const float4*)&Wu[tid << 2];
    __syncthreads();

    // Unary logits u[h][s] from global key rows; query column means mq[e].
#pragma unroll
    for (int u = 0; u < 2; u++) {
        int slot = tid + (u << 7);
        int s = slot & 63, h = slot >> 6;
        const float* kr = kg + (s << 6);
        float acc = __ldg(&bu[h]);
#pragma unroll
        for (int cc = 0; cc < 16; cc++) {
            float4 kv = *(const float4*)&kr[cc << 2];
            acc = fmaf(kv.x, sWu[((cc << 2) + 0) * 4 + h], acc);
            acc = fmaf(kv.y, sWu[((cc << 2) + 1) * 4 + h], acc);
            acc = fmaf(kv.z, sWu[((cc << 2) + 2) * 4 + h], acc);
            acc = fmaf(kv.w, sWu[((cc << 2) + 3) * 4 + h], acc);
        }
        susm[(h << 6) + s] = acc;
    }
    if (tid < 64) {
        float s = 0.0f;
#pragma unroll
        for (int r = 0; r < 64; r++) s += sQin[(r << 6) + tid];
        mq[tid] = s * (1.0f / 64.0f);
    }
    __syncthreads();

    // Unary softmax over fields s: warp w handles head w (4 warps).
    {
        int w = tid >> 5, lane = tid & 31;
        float v0 = susm[(w << 6) + lane];
        float v1 = susm[(w << 6) + 32 + lane];
        float m = fmaxf(v0, v1);
#pragma unroll
        for (int d = 16; d; d >>= 1)
            m = fmaxf(m, __shfl_xor_sync(0xffffffffu, m, d));
        float e0 = __expf(v0 - m), e1 = __expf(v1 - m);
        float s2 = e0 + e1;
#pragma unroll
        for (int d = 16; d; d >>= 1)
            s2 += __shfl_xor_sync(0xffffffffu, s2, d);
        float inv = 1.0f / s2;
        susm[(w << 6) + lane]      = e0 * inv;
        susm[(w << 6) + 32 + lane] = e1 * inv;
    }
    __syncthreads();

    // qc[a] = mq @ Wq[:,a]  (bq cancels exactly under Q-centering)
#pragma unroll
    for (int u = 0; u < 2; u++) {
        int aa = tid + (u << 7);
        float acc = 0.0f;
#pragma unroll
        for (int e = 0; e < 64; e++)
            acc = fmaf(mq[e], __ldg(&Wq[(e << 8) + aa]), acc);
        qc[aa] = acc;
    }
    __syncthreads();

#pragma unroll 1
    for (int h = 0; h < 4; h++) {
        const int hc = h << 6;

        // 1) stage Wq
        stage_w(sST, Wq, hc, tid);
        __syncthreads();

        // 2) Qh = qin @ Wq - qc   -> sQH
        {
            float acc[8][4];
            init_tile(acc, -qc[hc + C], -qc[hc + C + 1],
                      -qc[hc + C + 2], -qc[hc + C + 3]);
            gemm4(sQin, 64, sST, LDW, acc, R, C);
            store_w(sQH, acc, R, C);
        }
        __syncthreads();

        // 3) stage Wk
        stage_w(sST, Wk, hc, tid);
        __syncthreads();

        // 4) Kh = key @ Wk (global A) -> transposed into sKV (KhT[d][s])
        {
            float acc[8][4];
            init_tile(acc, 0.0f, 0.0f, 0.0f, 0.0f);
            gemm4(kg, 64, sST, LDW, acc, R, C);
#pragma unroll
            for (int j = 0; j < 4; j++)
#pragma unroll
                for (int i = 0; i < 8; i += 2)
                    *(float2*)&sKV[(C + j) * LDKV + R + i] =
                        make_float2(acc[i][j], acc[i + 1][j]);
        }
        __syncthreads();

        // 5) scores = Qh @ KhT (nn) -> regs; stage Wv into sQH after sync
        float sacc[8][4];
        init_tile(sacc, 0.0f, 0.0f, 0.0f, 0.0f);
        gemm2(sQH, LDW, sKV, LDKV, sacc, R, C);
        __syncthreads();            // all sQH/sKV reads complete
        store_w(sST, sacc, R, C);   // scores -> sST (Wk dead)
        stage_w(sQH, Wv, hc, tid);  // Wv -> sQH (Qh dead)
        __syncthreads();

        // 6) row softmax on sST + unary add (2 threads/row, rotated float4)
        {
            int row = tid >> 1, half = tid & 1;
            float* sr = &sST[row * LDW + (half << 5)];
            const float* ur = &susm[hc] + (half << 5);
            int rot = row & 7;
            float4 v[8];
#pragma unroll
            for (int cc = 0; cc < 8; cc++) {
                int c4 = ((cc + rot) & 7) << 2;
                v[cc] = *(const float4*)&sr[c4];
            }
            float m = -1e30f;
#pragma unroll
            for (int cc = 0; cc < 8; cc++)
                m = fmaxf(m, fmaxf(fmaxf(v[cc].x, v[cc].y), fmaxf(v[cc].z, v[cc].w)));
            m = fmaxf(m, __shfl_xor_sync(0xffffffffu, m, 1));
            float ssum = 0.0f;
#pragma unroll
            for (int cc = 0; cc < 8; cc++) {
                v[cc].x = __expf(v[cc].x - m);
                v[cc].y = __expf(v[cc].y - m);
                v[cc].z = __expf(v[cc].z - m);
                v[cc].w = __expf(v[cc].w - m);
                ssum += v[cc].x + v[cc].y + v[cc].z + v[cc].w;
            }
            ssum += __shfl_xor_sync(0xffffffffu, ssum, 1);
            float inv = 1.0f / ssum;
#pragma unroll
            for (int cc = 0; cc < 8; cc++) {
                int c4 = ((cc + rot) & 7) << 2;
                float4 u4 = *(const float4*)&ur[c4];
                float4 o;
                o.x = fmaf(v[cc].x, inv, u4.x);
                o.y = fmaf(v[cc].y, inv, u4.y);
                o.z = fmaf(v[cc].z, inv, u4.z);
                o.w = fmaf(v[cc].w, inv, u4.w);
                *(float4*)&sr[c4] = o;
            }
        }
        __syncthreads();

        // 7) Vh = value @ Wv (global A) + bv -> sKV (KhT dead), float2 stores
        {
            float acc[8][4];
            init_tile(acc, __ldg(&bv[hc + C]), __ldg(&bv[hc + C + 1]),
                      __ldg(&bv[hc + C + 2]), __ldg(&bv[hc + C + 3]));
            gemm4(vg, 64, sQH, LDW, acc, R, C);
#pragma unroll
            for (int i = 0; i < 8; i++) {
                *(float2*)&sKV[(R + i) * LDKV + C]     = make_float2(acc[i][0], acc[i][1]);
                *(float2*)&sKV[(R + i) * LDKV + C + 2] = make_float2(acc[i][2], acc[i][3]);
            }
        }
        __syncthreads();

        // 8) stage Wr into sQH (Wv dead)
        stage_w(sQH, Wr, hc, tid);
        __syncthreads();

        // 9) out = attn @ Vh + qin @ Wr + br
        {
            float acc[8][4];
            init_tile(acc, __ldg(&br[hc + C]), __ldg(&br[hc + C + 1]),
                      __ldg(&br[hc + C + 2]), __ldg(&br[hc + C + 3]));
            gemm2(sST, LDW, sKV, LDKV, acc, R, C);    // attn @ Vh
            gemm4(sQin, 64, sQH, LDW, acc, R, C);     // qin @ Wr

            float* og = out + (size_t)b * 16384 + R * 256 + hc + C;
#pragma unroll
            for (int i = 0; i < 8; i++)
                *(float4*)&og[i * 256] =
                    make_float4(acc[i][0], acc[i][1], acc[i][2], acc[i][3]);
        }
        __syncthreads();   // protect sST/sQH/sKV for next head
    }
}

extern "C" void kernel_launch(void* const* d_in, const int* in_sizes, int n_in,
                              void* d_out, int out_size) {
    const float* query = (const float*)d_in[0];
    const float* key_  = (const float*)d_in[1];
    const float* value = (const float*)d_in[2];
    const float* Wq    = (const float*)d_in[3];
    const float* bq    = (const float*)d_in[4];
    const float* Wk    = (const float*)d_in[5];
    const float* bk    = (const float*)d_in[6];
    const float* Wv    = (const float*)d_in[7];
    const float* bv    = (const float*)d_in[8];
    const float* Wu    = (const float*)d_in[9];
    const float* bu    = (const float*)d_in[10];
    const float* Wr    = (const float*)d_in[11];
    const float* br    = (const float*)d_in[12];
    float* out = (float*)d_out;
    (void)bq; (void)bk;

    size_t smem = SM_FLOATS * sizeof(float);   // ~69.75 KB -> 3 CTAs/SM
    cudaFuncSetAttribute(disattn_kernel,
                         cudaFuncAttributeMaxDynamicSharedMemorySize, (int)smem);
    disattn_kernel<<<4096, 128, smem>>>(query, key_, value, Wq, bq, Wk, bk,
                                        Wv, bv, Wu, bu, Wr, br, out);
}

// round 13
// speedup vs baseline: 2.0772x; 1.2526x over previous
#include <cuda_runtime.h>

// DisentangledSelfAttention, fused fp32, occupancy-oriented v2:
// 1 batch per CTA (grid 4096), 128 threads, ~54KB smem + <=128 regs
// -> 4 CTAs/SM (16 warps). All three input tiles (q/k/v) are read from
// global as A-operands (warp-broadcast LDG, L2-hot); only weight slices and
// intermediates live in smem, with aggressive buffer-role rotation.
// Algebra: K-centering + bk dropped (softmax-invariant); Q-centering folded
// via qc = mean(q)@Wq (bq cancels exactly).

#define LDW  68   // stage/QH stride (float4-aligned, conflict-free)
#define LDKV 66   // KhT/Vh stride (float2-aligned, 4-way store conflicts only)

#define O_ST  0
#define O_QH  (O_ST + 64 * LDW)     // 4352
#define O_KV  (O_QH + 64 * LDW)     // 8704
#define O_MQ  (O_KV + 64 * LDKV)    // 12928
#define O_QC  (O_MQ + 64)           // 12992
#define O_USM (O_QC + 256)          // 13248
#define O_WU  (O_USM + 256)         // 13504
#define SM_FLOATS (O_WU + 256)      // 13760 floats = 55040 B

// A (global or smem, row stride lda) x B (smem, stride ldb, float4 reads).
__device__ __forceinline__ void gemm4(const float* __restrict__ A, int lda,
                                      const float* __restrict__ B, int ldb,
                                      float acc[8][4], int R, int C) {
#pragma unroll
    for (int k = 0; k < 64; k += 4) {
        float4 a[8];
#pragma unroll
        for (int i = 0; i < 8; i++)
            a[i] = *(const float4*)&A[(R + i) * lda + k];
#pragma unroll
        for (int kk = 0; kk < 4; kk++) {
            float4 b4 = *(const float4*)&B[(k + kk) * ldb + C];
#pragma unroll
            for (int i = 0; i < 8; i++) {
                float av = (kk == 0) ? a[i].x : (kk == 1) ? a[i].y
                         : (kk == 2) ? a[i].z : a[i].w;
                acc[i][0] = fmaf(av, b4.x, acc[i][0]);
                acc[i][1] = fmaf(av, b4.y, acc[i][1]);
                acc[i][2] = fmaf(av, b4.z, acc[i][2]);
                acc[i][3] = fmaf(av, b4.w, acc[i][3]);
            }
        }
    }
}

// A (smem, stride lda, float4) x B (smem, stride ldb, float2 reads; ldb even).
__device__ __forceinline__ void gemm2(const float* __restrict__ A, int lda,
                                      const float* __restrict__ B, int ldb,
                                      float acc[8][4], int R, int C) {
#pragma unroll
    for (int k = 0; k < 64; k += 4) {
        float4 a[8];
#pragma unroll
        for (int i = 0; i < 8; i++) a[i] = *(const float4*)&A[(R + i) * lda + k];
#pragma unroll
        for (int kk = 0; kk < 4; kk++) {
            float2 bl = *(const float2*)&B[(k + kk) * ldb + C];
            float2 bh = *(const float2*)&B[(k + kk) * ldb + C + 2];
#pragma unroll
            for (int i = 0; i < 8; i++) {
                float av = (kk == 0) ? a[i].x : (kk == 1) ? a[i].y
                         : (kk == 2) ? a[i].z : a[i].w;
                acc[i][0] = fmaf(av, bl.x, acc[i][0]);
                acc[i][1] = fmaf(av, bl.y, acc[i][1]);
                acc[i][2] = fmaf(av, bh.x, acc[i][2]);
                acc[i][3] = fmaf(av, bh.y, acc[i][3]);
            }
        }
    }
}

__device__ __forceinline__ void init_tile(float acc[8][4], float v0, float v1,
                                          float v2, float v3) {
#pragma unroll
    for (int i = 0; i < 8; i++) {
        acc[i][0] = v0; acc[i][1] = v1; acc[i][2] = v2; acc[i][3] = v3;
    }
}

// float4 store, stride LDW (conflict-free).
__device__ __forceinline__ void store_w(float* __restrict__ dst,
                                        float acc[8][4], int R, int C) {
#pragma unroll
    for (int i = 0; i < 8; i++)
        *(float4*)&dst[(R + i) * LDW + C] =
            make_float4(acc[i][0], acc[i][1], acc[i][2], acc[i][3]);
}

// dst[e*LDW + c] = W[e*256 + hc + c],  e,c in [0,64); 128 threads.
__device__ __forceinline__ void stage_w(float* __restrict__ dst,
                                        const float* __restrict__ W,
                                        int hc, int tid) {
#pragma unroll
    for (int it = 0; it < 8; it++) {
        int i = tid + (it << 7);
        int e = i >> 4, c = (i & 15) << 2;
        *(float4*)&dst[e * LDW + c] = *(const float4*)&W[(e << 8) + hc + c];
    }
}

__global__ __launch_bounds__(128, 4)
void disattn_kernel(const float* __restrict__ query,
                    const float* __restrict__ key_,
                    const float* __restrict__ value,
                    const float* __restrict__ Wq, const float* __restrict__ bq,
                    const float* __restrict__ Wk, const float* __restrict__ bk,
                    const float* __restrict__ Wv, const float* __restrict__ bv,
                    const float* __restrict__ Wu, const float* __restrict__ bu,
                    const float* __restrict__ Wr, const float* __restrict__ br,
                    float* __restrict__ out) {
    extern __shared__ float sm[];
    float* sST  = sm + O_ST;    // Wq/Wk staging, then scores/attn
    float* sQH  = sm + O_QH;    // Qh, then Wv/Wr staging
    float* sKV  = sm + O_KV;    // KhT, then Vh
    float* mq   = sm + O_MQ;    // [64]
    float* qc   = sm + O_QC;    // [256]
    float* susm = sm + O_USM;   // [4][64]
    float* sWu  = sm + O_WU;    // [64][4]

    const int tid = threadIdx.x;
    const int b = blockIdx.x;
    const int tx = tid & 15, ty = tid >> 4;
    const int R = ty << 3, C = tx << 2;

    const float* qg = query + (size_t)b * 4096;
    const float* kg = key_  + (size_t)b * 4096;
    const float* vg = value + (size_t)b * 4096;

    // Prologue: Wu staging.
    if (tid < 64)
        *(float4*)&sWu[tid << 2] = *(const float4*)&Wu[tid << 2];

    // Unary logits u[h][s] from global key rows; query column means mq[e].
#pragma unroll
    for (int u = 0; u < 2; u++) {
        int slot = tid + (u << 7);
        int s = slot & 63, h = slot >> 6;
        const float* kr = kg + (s << 6);
        float acc = __ldg(&bu[h]);
#pragma unroll
        for (int cc = 0; cc < 16; cc++) {
            float4 kv = *(const float4*)&kr[cc << 2];
            const float* wu4 = (u == 0) ? &sWu[0] : &sWu[0];  // sWu written by tid<64 pre-sync
            acc = fmaf(kv.x, __ldg(&Wu[((cc << 2) + 0) * 4 + h]), acc);
            acc = fmaf(kv.y, __ldg(&Wu[((cc << 2) + 1) * 4 + h]), acc);
            acc = fmaf(kv.z, __ldg(&Wu[((cc << 2) + 2) * 4 + h]), acc);
            acc = fmaf(kv.w, __ldg(&Wu[((cc << 2) + 3) * 4 + h]), acc);
            (void)wu4;
        }
        susm[(h << 6) + s] = acc;
    }
    if (tid < 64) {
        float s = 0.0f;
#pragma unroll
        for (int r = 0; r < 64; r++) s += qg[(r << 6) + tid];
        mq[tid] = s * (1.0f / 64.0f);
    }
    __syncthreads();

    // Unary softmax over fields s: warp w handles head w (4 warps).
    {
        int w = tid >> 5, lane = tid & 31;
        float v0 = susm[(w << 6) + lane];
        float v1 = susm[(w << 6) + 32 + lane];
        float m = fmaxf(v0, v1);
#pragma unroll
        for (int d = 16; d; d >>= 1)
            m = fmaxf(m, __shfl_xor_sync(0xffffffffu, m, d));
        float e0 = __expf(v0 - m), e1 = __expf(v1 - m);
        float s2 = e0 + e1;
#pragma unroll
        for (int d = 16; d; d >>= 1)
            s2 += __shfl_xor_sync(0xffffffffu, s2, d);
        float inv = 1.0f / s2;
        susm[(w << 6) + lane]      = e0 * inv;
        susm[(w << 6) + 32 + lane] = e1 * inv;
    }

    // qc[a] = mq @ Wq[:,a]  (bq cancels exactly under Q-centering)
#pragma unroll
    for (int u = 0; u < 2; u++) {
        int aa = tid + (u << 7);
        float acc = 0.0f;
#pragma unroll
        for (int e = 0; e < 64; e++)
            acc = fmaf(mq[e], __ldg(&Wq[(e << 8) + aa]), acc);
        qc[aa] = acc;
    }
    __syncthreads();

#pragma unroll 1
    for (int h = 0; h < 4; h++) {
        const int hc = h << 6;

        // 1) stage Wq
        stage_w(sST, Wq, hc, tid);
        __syncthreads();

        // 2) Qh = q @ Wq - qc   (global A) -> sQH
        {
            float acc[8][4];
            init_tile(acc, -qc[hc + C], -qc[hc + C + 1],
                      -qc[hc + C + 2], -qc[hc + C + 3]);
            gemm4(qg, 64, sST, LDW, acc, R, C);
            store_w(sQH, acc, R, C);
        }
        __syncthreads();

        // 3) stage Wk
        stage_w(sST, Wk, hc, tid);
        __syncthreads();

        // 4) Kh = key @ Wk (global A) -> transposed into sKV (KhT[d][s])
        {
            float acc[8][4];
            init_tile(acc, 0.0f, 0.0f, 0.0f, 0.0f);
            gemm4(kg, 64, sST, LDW, acc, R, C);
#pragma unroll
            for (int j = 0; j < 4; j++)
#pragma unroll
                for (int i = 0; i < 8; i += 2)
                    *(float2*)&sKV[(C + j) * LDKV + R + i] =
                        make_float2(acc[i][j], acc[i + 1][j]);
        }
        __syncthreads();

        // 5) scores = Qh @ KhT (nn) -> regs; then stage Wv into sQH
        {
            float sacc[8][4];
            init_tile(sacc, 0.0f, 0.0f, 0.0f, 0.0f);
            gemm2(sQH, LDW, sKV, LDKV, sacc, R, C);
            __syncthreads();            // all sQH/sKV reads complete
            store_w(sST, sacc, R, C);   // scores -> sST (Wk dead)
        }
        stage_w(sQH, Wv, hc, tid);      // Wv -> sQH (Qh dead)
        __syncthreads();

        // 6) row softmax on sST + unary add (2 threads/row, rotated float4)
        {
            int row = tid >> 1, half = tid & 1;
            float* sr = &sST[row * LDW + (half << 5)];
            const float* ur = &susm[hc] + (half << 5);
            int rot = row & 7;
            float4 v[8];
#pragma unroll
            for (int cc = 0; cc < 8; cc++) {
                int c4 = ((cc + rot) & 7) << 2;
                v[cc] = *(const float4*)&sr[c4];
            }
            float m = -1e30f;
#pragma unroll
            for (int cc = 0; cc < 8; cc++)
                m = fmaxf(m, fmaxf(fmaxf(v[cc].x, v[cc].y), fmaxf(v[cc].z, v[cc].w)));
            m = fmaxf(m, __shfl_xor_sync(0xffffffffu, m, 1));
            float ssum = 0.0f;
#pragma unroll
            for (int cc = 0; cc < 8; cc++) {
                v[cc].x = __expf(v[cc].x - m);
                v[cc].y = __expf(v[cc].y - m);
                v[cc].z = __expf(v[cc].z - m);
                v[cc].w = __expf(v[cc].w - m);
                ssum += v[cc].x + v[cc].y + v[cc].z + v[cc].w;
            }
            ssum += __shfl_xor_sync(0xffffffffu, ssum, 1);
            float inv = 1.0f / ssum;
#pragma unroll
            for (int cc = 0; cc < 8; cc++) {
                int c4 = ((cc + rot) & 7) << 2;
                float4 u4 = *(const float4*)&ur[c4];
                float4 o;
                o.x = fmaf(v[cc].x, inv, u4.x);
                o.y = fmaf(v[cc].y, inv, u4.y);
                o.z = fmaf(v[cc].z, inv, u4.z);
                o.w = fmaf(v[cc].w, inv, u4.w);
                *(float4*)&sr[c4] = o;
            }
        }
        __syncthreads();

        // 7) Vh = value @ Wv (global A) + bv -> sKV (KhT dead), float2 stores
        {
            float acc[8][4];
            init_tile(acc, __ldg(&bv[hc + C]), __ldg(&bv[hc + C + 1]),
                      __ldg(&bv[hc + C + 2]), __ldg(&bv[hc + C + 3]));
            gemm4(vg, 64, sQH, LDW, acc, R, C);
#pragma unroll
            for (int i = 0; i < 8; i++) {
                *(float2*)&sKV[(R + i) * LDKV + C]     = make_float2(acc[i][0], acc[i][1]);
                *(float2*)&sKV[(R + i) * LDKV + C + 2] = make_float2(acc[i][2], acc[i][3]);
            }
        }
        __syncthreads();

        // 8) stage Wr into sQH (Wv dead)
        stage_w(sQH, Wr, hc, tid);
        __syncthreads();

        // 9) out = attn @ Vh + q @ Wr + br
        {
            float acc[8][4];
            init_tile(acc, __ldg(&br[hc + C]), __ldg(&br[hc + C + 1]),
                      __ldg(&br[hc + C + 2]), __ldg(&br[hc + C + 3]));
            gemm2(sST, LDW, sKV, LDKV, acc, R, C);    // attn @ Vh
            gemm4(qg, 64, sQH, LDW, acc, R, C);       // q @ Wr (global A)

            float* og = out + (size_t)b * 16384 + R * 256 + hc + C;
#pragma unroll
            for (int i = 0; i < 8; i++)
                *(float4*)&og[i * 256] =
                    make_float4(acc[i][0], acc[i][1], acc[i][2], acc[i][3]);
        }
        __syncthreads();   // protect sST/sQH/sKV for next head
    }
}

extern "C" void kernel_launch(void* const* d_in, const int* in_sizes, int n_in,
                              void* d_out, int out_size) {
    const float* query = (const float*)d_in[0];
    const float* key_  = (const float*)d_in[1];
    const float* value = (const float*)d_in[2];
    const float* Wq    = (const float*)d_in[3];
    const float* bq    = (const float*)d_in[4];
    const float* Wk    = (const float*)d_in[5];
    const float* bk    = (const float*)d_in[6];
    const float* Wv    = (const float*)d_in[7];
    const float* bv    = (const float*)d_in[8];
    const float* Wu    = (const float*)d_in[9];
    const float* bu    = (const float*)d_in[10];
    const float* Wr    = (const float*)d_in[11];
    const float* br    = (const float*)d_in[12];
    float* out = (float*)d_out;
    (void)bq; (void)bk;

    size_t smem = SM_FLOATS * sizeof(float);   // 55040 B -> 4 CTAs/SM
    cudaFuncSetAttribute(disattn_kernel,
                         cudaFuncAttributeMaxDynamicSharedMemorySize, (int)smem);
    disattn_kernel<<<4096, 128, smem>>>(query, key_, value, Wq, bq, Wk, bk,
                                        Wv, bv, Wu, bu, Wr, br, out);
}

// round 14
// speedup vs baseline: 2.1710x; 1.0451x over previous
#include <cuda_runtime.h>

// DisentangledSelfAttention, fused fp32, occupancy v2 + algebraic GEMM fusion.
// Precompute kernel: g_MT[h][c][e] = M_h[e][c], M_h = Wq_h @ Wk_h^T  (E x E,
// batch-independent). Main kernel (1 batch/CTA, 128 thr, ~53.5KB smem -> 4
// CTAs/SM): per head KM = k@M^T, scores = q@KM^T - mqKM (centering folded
// into column init), softmax, Vh = v@Wv, out = attn@Vh + q@Wr + br + u@Vh.
// bq/bk cancel (centering / softmax invariance); unary is rank-1 -> epilogue.

#define LDW  68   // staging + scores stride (float4, conflict-free)
#define LDKV 66   // KMT/Vh stride (float2, 4-way store conflicts only)

#define O_A   0                     // staging: MT / Wv / Wr
#define O_C   (O_A + 64 * LDW)      // scores / attn
#define O_B   (O_C + 64 * LDW)      // KMT, then Vh
#define O_MQ  (O_B + 64 * LDKV)     // [64]
#define O_MQK (O_MQ + 64)           // [64] mqKM
#define O_UV  (O_MQK + 64)          // [64] u@Vh
#define O_USM (O_UV + 64)           // [4][64]
#define SM_FLOATS (O_USM + 256)     // 13376 floats = 53504 B

__device__ float g_MT[4 * 64 * 64];   // [h][c][e] = M_h[e][c]

__global__ __launch_bounds__(256) void precompute_MT(const float* __restrict__ Wq,
                                                     const float* __restrict__ Wk) {
    __shared__ float sq[64 * 68], sk[64 * 68];
    const int h = blockIdx.x, hc = h << 6, tid = threadIdx.x;
#pragma unroll
    for (int it = 0; it < 4; it++) {
        int i = tid + (it << 8);
        int e = i >> 4, a = (i & 15) << 2;
        *(float4*)&sq[e * 68 + a] = *(const float4*)&Wq[(e << 8) + hc + a];
        *(float4*)&sk[e * 68 + a] = *(const float4*)&Wk[(e << 8) + hc + a];
    }
    __syncthreads();
#pragma unroll
    for (int it = 0; it < 16; it++) {
        int idx = tid + (it << 8);
        int c = idx >> 6, e = idx & 63;
        float acc = 0.0f;
#pragma unroll
        for (int a = 0; a < 64; a += 4) {
            float4 qa = *(const float4*)&sq[e * 68 + a];
            float4 ka = *(const float4*)&sk[c * 68 + a];
            acc = fmaf(qa.x, ka.x, acc);
            acc = fmaf(qa.y, ka.y, acc);
            acc = fmaf(qa.z, ka.z, acc);
            acc = fmaf(qa.w, ka.w, acc);
        }
        g_MT[(h << 12) + (c << 6) + e] = acc;   // MT[c][e] = M[e][c]
    }
}

// A (global or smem, stride lda) x B (smem, stride ldb, float4 reads).
__device__ __forceinline__ void gemm4(const float* __restrict__ A, int lda,
                                      const float* __restrict__ B, int ldb,
                                      float acc[8][4], int R, int C) {
#pragma unroll
    for (int k = 0; k < 64; k += 4) {
        float4 a[8];
#pragma unroll
        for (int i = 0; i < 8; i++)
            a[i] = *(const float4*)&A[(R + i) * lda + k];
#pragma unroll
        for (int kk = 0; kk < 4; kk++) {
            float4 b4 = *(const float4*)&B[(k + kk) * ldb + C];
#pragma unroll
            for (int i = 0; i < 8; i++) {
                float av = (kk == 0) ? a[i].x : (kk == 1) ? a[i].y
                         : (kk == 2) ? a[i].z : a[i].w;
                acc[i][0] = fmaf(av, b4.x, acc[i][0]);
                acc[i][1] = fmaf(av, b4.y, acc[i][1]);
                acc[i][2] = fmaf(av, b4.z, acc[i][2]);
                acc[i][3] = fmaf(av, b4.w, acc[i][3]);
            }
        }
    }
}

// A (global or smem, stride lda, float4) x B (smem, stride ldb even, float2).
__device__ __forceinline__ void gemm2(const float* __restrict__ A, int lda,
                                      const float* __restrict__ B, int ldb,
                                      float acc[8][4], int R, int C) {
#pragma unroll
    for (int k = 0; k < 64; k += 4) {
        float4 a[8];
#pragma unroll
        for (int i = 0; i < 8; i++) a[i] = *(const float4*)&A[(R + i) * lda + k];
#pragma unroll
        for (int kk = 0; kk < 4; kk++) {
            float2 bl = *(const float2*)&B[(k + kk) * ldb + C];
            float2 bh = *(const float2*)&B[(k + kk) * ldb + C + 2];
#pragma unroll
            for (int i = 0; i < 8; i++) {
                float av = (kk == 0) ? a[i].x : (kk == 1) ? a[i].y
                         : (kk == 2) ? a[i].z : a[i].w;
                acc[i][0] = fmaf(av, bl.x, acc[i][0]);
                acc[i][1] = fmaf(av, bl.y, acc[i][1]);
                acc[i][2] = fmaf(av, bh.x, acc[i][2]);
                acc[i][3] = fmaf(av, bh.y, acc[i][3]);
            }
        }
    }
}

__device__ __forceinline__ void init_tile(float acc[8][4], float v0, float v1,
                                          float v2, float v3) {
#pragma unroll
    for (int i = 0; i < 8; i++) {
        acc[i][0] = v0; acc[i][1] = v1; acc[i][2] = v2; acc[i][3] = v3;
    }
}

__device__ __forceinline__ void store_w(float* __restrict__ dst,
                                        float acc[8][4], int R, int C) {
#pragma unroll
    for (int i = 0; i < 8; i++)
        *(float4*)&dst[(R + i) * LDW + C] =
            make_float4(acc[i][0], acc[i][1], acc[i][2], acc[i][3]);
}

// dst[e*LDW + c] = W[e*256 + hc + c]; 128 threads.
__device__ __forceinline__ void stage_w(float* __restrict__ dst,
                                        const float* __restrict__ W,
                                        int hc, int tid) {
#pragma unroll
    for (int it = 0; it < 8; it++) {
        int i = tid + (it << 7);
        int e = i >> 4, c = (i & 15) << 2;
        *(float4*)&dst[e * LDW + c] = *(const float4*)&W[(e << 8) + hc + c];
    }
}

// dst[c*LDW + e] = g_MT[h][c][e]; 128 threads.
__device__ __forceinline__ void stage_mt(float* __restrict__ dst, int h, int tid) {
#pragma unroll
    for (int it = 0; it < 8; it++) {
        int i = tid + (it << 7);
        int c = i >> 4, e = (i & 15) << 2;
        *(float4*)&dst[c * LDW + e] = *(const float4*)&g_MT[(h << 12) + (c << 6) + e];
    }
}

__global__ __launch_bounds__(128, 4)
void disattn_kernel(const float* __restrict__ query,
                    const float* __restrict__ key_,
                    const float* __restrict__ value,
                    const float* __restrict__ Wv, const float* __restrict__ bv,
                    const float* __restrict__ Wu, const float* __restrict__ bu,
                    const float* __restrict__ Wr, const float* __restrict__ br,
                    float* __restrict__ out) {
    extern __shared__ float sm[];
    float* sA   = sm + O_A;     // MT / Wv / Wr staging
    float* sC   = sm + O_C;     // scores / attn
    float* sB   = sm + O_B;     // KMT then Vh
    float* mq   = sm + O_MQ;
    float* mqKM = sm + O_MQK;
    float* uV   = sm + O_UV;
    float* susm = sm + O_USM;

    const int tid = threadIdx.x;
    const int b = blockIdx.x;
    const int tx = tid & 15, ty = tid >> 4;
    const int R = ty << 3, C = tx << 2;

    const float* qg = query + (size_t)b * 4096;
    const float* kg = key_  + (size_t)b * 4096;
    const float* vg = value + (size_t)b * 4096;

    // Prologue: unary logits u[h][s] + query column means mq[e].
#pragma unroll
    for (int u = 0; u < 2; u++) {
        int slot = tid + (u << 7);
        int s = slot & 63, h = slot >> 6;
        const float* kr = kg + (s << 6);
        float acc = __ldg(&bu[h]);
#pragma unroll
        for (int cc = 0; cc < 16; cc++) {
            float4 kv = *(const float4*)&kr[cc << 2];
            acc = fmaf(kv.x, __ldg(&Wu[((cc << 2) + 0) * 4 + h]), acc);
            acc = fmaf(kv.y, __ldg(&Wu[((cc << 2) + 1) * 4 + h]), acc);
            acc = fmaf(kv.z, __ldg(&Wu[((cc << 2) + 2) * 4 + h]), acc);
            acc = fmaf(kv.w, __ldg(&Wu[((cc << 2) + 3) * 4 + h]), acc);
        }
        susm[(h << 6) + s] = acc;
    }
    if (tid < 64) {
        float s = 0.0f;
#pragma unroll
        for (int r = 0; r < 64; r++) s += qg[(r << 6) + tid];
        mq[tid] = s * (1.0f / 64.0f);
    }
    __syncthreads();

    // Unary softmax over fields s: warp w = head w.
    {
        int w = tid >> 5, lane = tid & 31;
        float v0 = susm[(w << 6) + lane];
        float v1 = susm[(w << 6) + 32 + lane];
        float m = fmaxf(v0, v1);
#pragma unroll
        for (int d = 16; d; d >>= 1)
            m = fmaxf(m, __shfl_xor_sync(0xffffffffu, m, d));
        float e0 = __expf(v0 - m), e1 = __expf(v1 - m);
        float s2 = e0 + e1;
#pragma unroll
        for (int d = 16; d; d >>= 1)
            s2 += __shfl_xor_sync(0xffffffffu, s2, d);
        float inv = 1.0f / s2;
        susm[(w << 6) + lane]      = e0 * inv;
        susm[(w << 6) + 32 + lane] = e1 * inv;
    }
    __syncthreads();

#pragma unroll 1
    for (int h = 0; h < 4; h++) {
        const int hc = h << 6;

        // a) stage MT_h
        stage_mt(sA, h, tid);
        __syncthreads();

        // b) KM = k @ MT (global A) -> transposed store KMT[e][t] into sB
        {
            float acc[8][4];
            init_tile(acc, 0.0f, 0.0f, 0.0f, 0.0f);
            gemm4(kg, 64, sA, LDW, acc, R, C);
#pragma unroll
            for (int j = 0; j < 4; j++)
#pragma unroll
                for (int i = 0; i < 8; i += 2)
                    *(float2*)&sB[(C + j) * LDKV + R + i] =
                        make_float2(acc[i][j], acc[i + 1][j]);
        }
        __syncthreads();

        // c) mqKM[t] = sum_e mq[e]*KMT[e][t]  (2 thr/t); stage Wv -> sA
        {
            int t = tid >> 1, e0 = (tid & 1) << 5;
            float s = 0.0f;
#pragma unroll
            for (int e = 0; e < 32; e++)
                s = fmaf(mq[e0 + e], sB[(e0 + e) * LDKV + t], s);
            s += __shfl_xor_sync(0xffffffffu, s, 1);
            if ((tid & 1) == 0) mqKM[t] = s;
        }
        stage_w(sA, Wv, hc, tid);
        __syncthreads();

        // d) scores = q @ KMT - mqKM (global A, float2 B) -> sC
        {
            float sacc[8][4];
            init_tile(sacc, -mqKM[C], -mqKM[C + 1], -mqKM[C + 2], -mqKM[C + 3]);
            gemm2(qg, 64, sB, LDKV, sacc, R, C);
            store_w(sC, sacc, R, C);
        }
        __syncthreads();

        // e) row softmax on sC (2 threads/row, rotated float4), no unary add
        {
            int row = tid >> 1, half = tid & 1;
            float* sr = &sC[row * LDW + (half << 5)];
            int rot = row & 7;
            float4 v[8];
#pragma unroll
            for (int cc = 0; cc < 8; cc++) {
                int c4 = ((cc + rot) & 7) << 2;
                v[cc] = *(const float4*)&sr[c4];
            }
            float m = -1e30f;
#pragma unroll
            for (int cc = 0; cc < 8; cc++)
                m = fmaxf(m, fmaxf(fmaxf(v[cc].x, v[cc].y), fmaxf(v[cc].z, v[cc].w)));
            m = fmaxf(m, __shfl_xor_sync(0xffffffffu, m, 1));
            float ssum = 0.0f;
#pragma unroll
            for (int cc = 0; cc < 8; cc++) {
                v[cc].x = __expf(v[cc].x - m);
                v[cc].y = __expf(v[cc].y - m);
                v[cc].z = __expf(v[cc].z - m);
                v[cc].w = __expf(v[cc].w - m);
                ssum += v[cc].x + v[cc].y + v[cc].z + v[cc].w;
            }
            ssum += __shfl_xor_sync(0xffffffffu, ssum, 1);
            float inv = 1.0f / ssum;
#pragma unroll
            for (int cc = 0; cc < 8; cc++) {
                int c4 = ((cc + rot) & 7) << 2;
                v[cc].x *= inv; v[cc].y *= inv; v[cc].z *= inv; v[cc].w *= inv;
                *(float4*)&sr[c4] = v[cc];
            }
        }
        __syncthreads();

        // f) Vh = v @ Wv + bv (global A) -> sB (KMT dead), float2 stores
        {
            float acc[8][4];
            init_tile(acc, __ldg(&bv[hc + C]), __ldg(&bv[hc + C + 1]),
                      __ldg(&bv[hc + C + 2]), __ldg(&bv[hc + C + 3]));
            gemm4(vg, 64, sA, LDW, acc, R, C);
#pragma unroll
            for (int i = 0; i < 8; i++) {
                *(float2*)&sB[(R + i) * LDKV + C]     = make_float2(acc[i][0], acc[i][1]);
                *(float2*)&sB[(R + i) * LDKV + C + 2] = make_float2(acc[i][2], acc[i][3]);
            }
        }
        __syncthreads();

        // g) uV[c] = sum_t u[t]*Vh[t][c]  (2 thr/c); stage Wr -> sA
        {
            int c = tid >> 1, t0 = (tid & 1) << 5;
            float s = 0.0f;
#pragma unroll
            for (int t = 0; t < 32; t++)
                s = fmaf(susm[hc + t0 + t], sB[(t0 + t) * LDKV + c], s);
            s += __shfl_xor_sync(0xffffffffu, s, 1);
            if ((tid & 1) == 0) uV[c] = s;
        }
        stage_w(sA, Wr, hc, tid);
        __syncthreads();

        // h) out = attn @ Vh + q @ Wr + br + uV
        {
            float acc[8][4];
            init_tile(acc,
                      __ldg(&br[hc + C])     + uV[C],
                      __ldg(&br[hc + C + 1]) + uV[C + 1],
                      __ldg(&br[hc + C + 2]) + uV[C + 2],
                      __ldg(&br[hc + C + 3]) + uV[C + 3]);
            gemm2(sC, LDW, sB, LDKV, acc, R, C);   // attn @ Vh
            gemm4(qg, 64, sA, LDW, acc, R, C);     // q @ Wr

            float* og = out + (size_t)b * 16384 + R * 256 + hc + C;
#pragma unroll
            for (int i = 0; i < 8; i++)
                *(float4*)&og[i * 256] =
                    make_float4(acc[i][0], acc[i][1], acc[i][2], acc[i][3]);
        }
        __syncthreads();
    }
}

extern "C" void kernel_launch(void* const* d_in, const int* in_sizes, int n_in,
                              void* d_out, int out_size) {
    const float* query = (const float*)d_in[0];
    const float* key_  = (const float*)d_in[1];
    const float* value = (const float*)d_in[2];
    const float* Wq    = (const float*)d_in[3];
    const float* Wk    = (const float*)d_in[5];
    const float* Wv    = (const float*)d_in[7];
    const float* bv    = (const float*)d_in[8];
    const float* Wu    = (const float*)d_in[9];
    const float* bu    = (const float*)d_in[10];
    const float* Wr    = (const float*)d_in[11];
    const float* br    = (const float*)d_in[12];
    float* out = (float*)d_out;

    precompute_MT<<<4, 256>>>(Wq, Wk);

    size_t smem = SM_FLOATS * sizeof(float);   // 53504 B -> 4 CTAs/SM
    cudaFuncSetAttribute(disattn_kernel,
                         cudaFuncAttributeMaxDynamicSharedMemorySize, (int)smem);
    disattn_kernel<<<4096, 128, smem>>>(query, key_, value, Wv, bv,
                                        Wu, bu, Wr, br, out);
}